// round 2
// baseline (speedup 1.0000x reference)
#include <cuda_runtime.h>
#include <math.h>

// Problem constants
#define M_TOT   12288      // B*S
#define K_FC1   768        // D
#define H_DIM   3072       // hidden
#define N_SHARED 512
#define N_PART  256
#define D_OUT   768
#define S_LEN   192
#define B_TOT   64

// Intermediate h = gelu(fc1(x)) : [12288, 3072] fp32 (static device scratch; no runtime alloc)
static __device__ float g_h[(size_t)M_TOT * H_DIM];
// Decoded expert indices (robust to int32-vs-int64 on the wire)
static __device__ int g_idx[B_TOT];

__device__ __forceinline__ float gelu_erf(float x) {
    return 0.5f * x * (1.0f + erff(x * 0.70710678118654752440f));
}

// ---------------------------------------------------------------------------
// Kernel 0: decode indices. JAX default disables x64, so the "int64" indices
// are most likely int32 on the wire. Detect: if the buffer were int64 with
// small values, every odd int32 word (hi half) is 0. Under int32 data the
// odds of all 32 odd words being 0 is (1/6)^32 ~ 0.
// ---------------------------------------------------------------------------
__global__ void decode_idx_kernel(const int* __restrict__ raw)
{
    __shared__ int is64;
    if (threadIdx.x == 0) {
        int odd_or = 0;
        for (int i = 1; i < B_TOT; i += 2) odd_or |= raw[i];
        is64 = (odd_or == 0) ? 1 : 0;
    }
    __syncthreads();
    int b = threadIdx.x;   // 64 threads
    g_idx[b] = is64 ? raw[2 * b] : raw[b];
}

// ---------------------------------------------------------------------------
// Kernel 1: h = gelu(A @ W^T + b)
//   A: [12288, 768] row-major (K contiguous)
//   W: [3072, 768]  row-major (K contiguous)  -> out [12288, 3072]
// Tile 128x128, K-step 8, 256 threads, 8x8 micro-tile.
// ---------------------------------------------------------------------------
__global__ void __launch_bounds__(256) fc1_gelu_kernel(
    const float* __restrict__ A,
    const float* __restrict__ W,
    const float* __restrict__ bias)
{
    __shared__ float As[8][132];   // stride 132: conflict-free STS for k-phases {0,4}
    __shared__ float Bs[8][132];

    const int tid = threadIdx.x;
    const int bm = blockIdx.y * 128;
    const int bn = blockIdx.x * 128;

    // global load mapping: each thread loads one float4 of A and one of W per stage
    const int l_m = tid >> 1;          // 0..127
    const int l_k = (tid & 1) * 4;     // 0 or 4

    const float* Ap = A + (size_t)(bm + l_m) * K_FC1 + l_k;
    const float* Wp = W + (size_t)(bn + l_m) * K_FC1 + l_k;

    const int tx = tid & 15;   // column group
    const int ty = tid >> 4;   // row group

    float acc[8][8];
#pragma unroll
    for (int i = 0; i < 8; i++)
#pragma unroll
        for (int j = 0; j < 8; j++) acc[i][j] = 0.f;

    float4 a_reg = *(const float4*)Ap;
    float4 b_reg = *(const float4*)Wp;

    for (int k0 = 0; k0 < K_FC1; k0 += 8) {
        __syncthreads();
        As[l_k + 0][l_m] = a_reg.x;
        As[l_k + 1][l_m] = a_reg.y;
        As[l_k + 2][l_m] = a_reg.z;
        As[l_k + 3][l_m] = a_reg.w;
        Bs[l_k + 0][l_m] = b_reg.x;
        Bs[l_k + 1][l_m] = b_reg.y;
        Bs[l_k + 2][l_m] = b_reg.z;
        Bs[l_k + 3][l_m] = b_reg.w;
        __syncthreads();

        if (k0 + 8 < K_FC1) {
            a_reg = *(const float4*)(Ap + k0 + 8);
            b_reg = *(const float4*)(Wp + k0 + 8);
        }

#pragma unroll
        for (int kk = 0; kk < 8; kk++) {
            float4 a0 = *(const float4*)&As[kk][ty * 4];
            float4 a1 = *(const float4*)&As[kk][64 + ty * 4];
            float4 b0 = *(const float4*)&Bs[kk][tx * 4];
            float4 b1 = *(const float4*)&Bs[kk][64 + tx * 4];
            float av[8] = {a0.x, a0.y, a0.z, a0.w, a1.x, a1.y, a1.z, a1.w};
            float bv[8] = {b0.x, b0.y, b0.z, b0.w, b1.x, b1.y, b1.z, b1.w};
#pragma unroll
            for (int i = 0; i < 8; i++)
#pragma unroll
                for (int j = 0; j < 8; j++)
                    acc[i][j] = fmaf(av[i], bv[j], acc[i][j]);
        }
    }

    // Epilogue: bias + exact GELU, vectorized float4 stores
    const int c0 = bn + tx * 4;
    const int c1 = bn + 64 + tx * 4;
    float4 bias0 = *(const float4*)&bias[c0];
    float4 bias1 = *(const float4*)&bias[c1];
#pragma unroll
    for (int half = 0; half < 2; half++) {
#pragma unroll
        for (int i = 0; i < 4; i++) {
            int r = bm + half * 64 + ty * 4 + i;
            int ai = half * 4 + i;
            float4 o0, o1;
            o0.x = gelu_erf(acc[ai][0] + bias0.x);
            o0.y = gelu_erf(acc[ai][1] + bias0.y);
            o0.z = gelu_erf(acc[ai][2] + bias0.z);
            o0.w = gelu_erf(acc[ai][3] + bias0.w);
            o1.x = gelu_erf(acc[ai][4] + bias1.x);
            o1.y = gelu_erf(acc[ai][5] + bias1.y);
            o1.z = gelu_erf(acc[ai][6] + bias1.z);
            o1.w = gelu_erf(acc[ai][7] + bias1.w);
            float* hrow = g_h + (size_t)r * H_DIM;
            *(float4*)&hrow[c0] = o0;
            *(float4*)&hrow[c1] = o1;
        }
    }
}

// ---------------------------------------------------------------------------
// Kernel 2: fused shared fc2 + expert GEMM.
//   out[:, 0:512]   = h @ fc2_w^T + fc2_b
//   out[:, 512:768] = h @ expert_w[idx[b]]^T + expert_b[idx[b]]
// M-tile 64 (stays within one batch: 192 = 3*64), N-tile 128, K-step 8,
// 256 threads, 4x8 micro-tile. Both weight matrices are K-contiguous,
// so only the base pointer differs per N-tile.
// ---------------------------------------------------------------------------
__global__ void __launch_bounds__(256) fc2_expert_kernel(
    const float* __restrict__ fc2_w,
    const float* __restrict__ fc2_b,
    const float* __restrict__ ew,
    const float* __restrict__ eb,
    float* __restrict__ out)
{
    __shared__ float As[8][68];    // stride 68: conflict-free for k-phases {0,2,4,6}
    __shared__ float Bs[8][132];

    const int tid = threadIdx.x;
    const int bm = blockIdx.y * 64;          // global row (within one batch)
    const int bn = blockIdx.x * 128;         // global output column
    const int batch = bm / S_LEN;

    const float* Wbase;
    const float* biasp;
    if (bn < N_SHARED) {
        Wbase = fc2_w + (size_t)bn * H_DIM;
        biasp = fc2_b + bn;
    } else {
        const int e = g_idx[batch];
        Wbase = ew + ((size_t)e * N_PART + (bn - N_SHARED)) * H_DIM;
        biasp = eb + (size_t)e * N_PART + (bn - N_SHARED);
    }
    const float* Abase = g_h + (size_t)bm * H_DIM;

    // global load mapping
    const int am = tid >> 2;          // 0..63
    const int ak = (tid & 3) * 2;     // 0,2,4,6
    const int wn = tid >> 1;          // 0..127
    const int wk = (tid & 1) * 4;     // 0 or 4

    const float* Ap = Abase + (size_t)am * H_DIM + ak;
    const float* Wp = Wbase + (size_t)wn * H_DIM + wk;

    const int tx = tid & 15;
    const int ty = tid >> 4;

    float acc[4][8];
#pragma unroll
    for (int i = 0; i < 4; i++)
#pragma unroll
        for (int j = 0; j < 8; j++) acc[i][j] = 0.f;

    float2 a_reg = *(const float2*)Ap;
    float4 b_reg = *(const float4*)Wp;

    for (int k0 = 0; k0 < H_DIM; k0 += 8) {
        __syncthreads();
        As[ak + 0][am] = a_reg.x;
        As[ak + 1][am] = a_reg.y;
        Bs[wk + 0][wn] = b_reg.x;
        Bs[wk + 1][wn] = b_reg.y;
        Bs[wk + 2][wn] = b_reg.z;
        Bs[wk + 3][wn] = b_reg.w;
        __syncthreads();

        if (k0 + 8 < H_DIM) {
            a_reg = *(const float2*)(Ap + k0 + 8);
            b_reg = *(const float4*)(Wp + k0 + 8);
        }

#pragma unroll
        for (int kk = 0; kk < 8; kk++) {
            float4 a0 = *(const float4*)&As[kk][ty * 4];
            float4 b0 = *(const float4*)&Bs[kk][tx * 4];
            float4 b1 = *(const float4*)&Bs[kk][64 + tx * 4];
            float av[4] = {a0.x, a0.y, a0.z, a0.w};
            float bv[8] = {b0.x, b0.y, b0.z, b0.w, b1.x, b1.y, b1.z, b1.w};
#pragma unroll
            for (int i = 0; i < 4; i++)
#pragma unroll
                for (int j = 0; j < 8; j++)
                    acc[i][j] = fmaf(av[i], bv[j], acc[i][j]);
        }
    }

    // Epilogue: bias + vectorized stores
    float4 bias0 = *(const float4*)(biasp + tx * 4);
    float4 bias1 = *(const float4*)(biasp + 64 + tx * 4);
#pragma unroll
    for (int i = 0; i < 4; i++) {
        const int r = bm + ty * 4 + i;
        float4 o0, o1;
        o0.x = acc[i][0] + bias0.x;
        o0.y = acc[i][1] + bias0.y;
        o0.z = acc[i][2] + bias0.z;
        o0.w = acc[i][3] + bias0.w;
        o1.x = acc[i][4] + bias1.x;
        o1.y = acc[i][5] + bias1.y;
        o1.z = acc[i][6] + bias1.z;
        o1.w = acc[i][7] + bias1.w;
        float* orow = out + (size_t)r * D_OUT;
        *(float4*)&orow[bn + tx * 4] = o0;
        *(float4*)&orow[bn + 64 + tx * 4] = o1;
    }
}

// ---------------------------------------------------------------------------
// Launch: inputs per metadata order:
// 0 hidden_state f32 [64,192,768], 1 indices (int32 or int64) [64],
// 2 fc1_w [3072,768], 3 fc1_b [3072], 4 fc2_w [512,3072], 5 fc2_b [512],
// 6 expert_w [6,256,3072], 7 expert_b [6,256]; out f32 [64,192,768]
// ---------------------------------------------------------------------------
extern "C" void kernel_launch(void* const* d_in, const int* in_sizes, int n_in,
                              void* d_out, int out_size)
{
    (void)in_sizes; (void)n_in; (void)out_size;
    const float* hs    = (const float*)d_in[0];
    const int*   raw   = (const int*)d_in[1];
    const float* fc1_w = (const float*)d_in[2];
    const float* fc1_b = (const float*)d_in[3];
    const float* fc2_w = (const float*)d_in[4];
    const float* fc2_b = (const float*)d_in[5];
    const float* ew    = (const float*)d_in[6];
    const float* eb    = (const float*)d_in[7];
    float*       out   = (float*)d_out;

    decode_idx_kernel<<<1, B_TOT>>>(raw);

    dim3 g1(H_DIM / 128, M_TOT / 128);   // (24, 96)
    fc1_gelu_kernel<<<g1, 256>>>(hs, fc1_w, fc1_b);

    dim3 g2(D_OUT / 128, M_TOT / 64);    // (6, 192)
    fc2_expert_kernel<<<g2, 256>>>(fc2_w, fc2_b, ew, eb, out);
}

// round 4
// speedup vs baseline: 2.4562x; 2.4562x over previous
#include <cuda_runtime.h>
#include <math.h>
#include <stdint.h>

// ---------------- problem constants ----------------
#define M_TOT   12288
#define K1      768
#define H_DIM   3072
#define N_SHARED 512
#define N_PART  256
#define D_OUT   768
#define S_LEN   192
#define B_TOT   64

// ---------------- tiling ----------------
#define BM 128
#define BN 128
#define BK 32
#define TSTRIDE 36                    // floats; conflict-free frag LDS (banks 4g+t)
#define TILE_F  (128 * TSTRIDE)       // floats per (buffer, operand)
#define SMEM_BYTES (4 * TILE_F * 4)   // A0,A1,B0,B1 = 73728 B

// ---------------- device scratch ----------------
static __device__ float g_h[(size_t)M_TOT * H_DIM];
static __device__ int g_idx[B_TOT];

// ---------------- helpers ----------------
__device__ __forceinline__ float to_tf32(float x) {
    float r; asm("cvt.rna.tf32.f32 %0, %1;" : "=f"(r) : "f"(x)); return r;
}
__device__ __forceinline__ float gelu_erf(float x) {
    return 0.5f * x * (1.0f + erff(x * 0.70710678118654752440f));
}
__device__ __forceinline__ void mma_tf32(float* c, const uint32_t* a, const uint32_t* b) {
    asm volatile(
        "mma.sync.aligned.m16n8k8.row.col.f32.tf32.tf32.f32 "
        "{%0,%1,%2,%3}, {%4,%5,%6,%7}, {%8,%9}, {%0,%1,%2,%3};"
        : "+f"(c[0]), "+f"(c[1]), "+f"(c[2]), "+f"(c[3])
        : "r"(a[0]), "r"(a[1]), "r"(a[2]), "r"(a[3]), "r"(b[0]), "r"(b[1]));
}

// ---------------- index decode (verified R2: indices are int32 on the wire) ----------------
__global__ void decode_idx_kernel(const int* __restrict__ raw)
{
    __shared__ int is64;
    if (threadIdx.x == 0) {
        int odd_or = 0;
        for (int i = 1; i < B_TOT; i += 2) odd_or |= raw[i];
        is64 = (odd_or == 0) ? 1 : 0;
    }
    __syncthreads();
    int b = threadIdx.x;
    g_idx[b] = is64 ? raw[2 * b] : raw[b];
}

// ---------------- tf32 mma.sync GEMM: D[128,128] = A[128,K] @ B[128,K]^T (+bias, opt GELU) ----
// A, B row-major K-contiguous. 256 threads, 8 warps 4(M)x2(N), warp tile 32x64.
template <bool GELU>
__device__ __forceinline__ void gemm_tf32(
    const float* __restrict__ A, int ldA,
    const float* __restrict__ B, int ldB,
    int K,
    float* __restrict__ out, int ldOut,
    const float* __restrict__ bias)
{
    extern __shared__ float sm[];
    const int tid  = threadIdx.x;
    const int lane = tid & 31;
    const int wid  = tid >> 5;
    const int g = lane >> 2;     // mma "group" (row/col within 8)
    const int t = lane & 3;      // thread-in-group (k quarter / col pair)
    const int wm = wid & 3;      // warp rows: wm*32
    const int wn = wid >> 2;     // warp cols: wn*64

    // gmem<->smem mapping: 4 iters, row = i*32 + (tid>>3), float4 col c4 = tid&7
    const int r0 = tid >> 3;
    const int c4 = tid & 7;

    float acc[2][8][4];
#pragma unroll
    for (int mt = 0; mt < 2; mt++)
#pragma unroll
        for (int nt = 0; nt < 8; nt++)
#pragma unroll
            for (int q = 0; q < 4; q++) acc[mt][nt][q] = 0.f;

    const int NS = K / BK;
    float4 ra[4], rb[4];

    // prologue: stage 0
#pragma unroll
    for (int i = 0; i < 4; i++) {
        ra[i] = *(const float4*)(A + (size_t)(i * 32 + r0) * ldA + c4 * 4);
        rb[i] = *(const float4*)(B + (size_t)(i * 32 + r0) * ldB + c4 * 4);
    }
    {
        float* as = sm;
        float* bs = sm + 2 * TILE_F;
#pragma unroll
        for (int i = 0; i < 4; i++) {
            const int o = (i * 32 + r0) * TSTRIDE + c4 * 4;
            as[o+0]=to_tf32(ra[i].x); as[o+1]=to_tf32(ra[i].y); as[o+2]=to_tf32(ra[i].z); as[o+3]=to_tf32(ra[i].w);
            bs[o+0]=to_tf32(rb[i].x); bs[o+1]=to_tf32(rb[i].y); bs[o+2]=to_tf32(rb[i].z); bs[o+3]=to_tf32(rb[i].w);
        }
    }
    __syncthreads();

    for (int s = 0; s < NS; s++) {
        if (s + 1 < NS) {
            const int k0 = (s + 1) * BK;
#pragma unroll
            for (int i = 0; i < 4; i++) {
                ra[i] = *(const float4*)(A + (size_t)(i * 32 + r0) * ldA + k0 + c4 * 4);
                rb[i] = *(const float4*)(B + (size_t)(i * 32 + r0) * ldB + k0 + c4 * 4);
            }
        }

        // compute current buffer
        {
            const int buf = s & 1;
            const float* as = sm + buf * TILE_F + (wm * 32) * TSTRIDE;
            const float* bs = sm + 2 * TILE_F + buf * TILE_F + (wn * 64) * TSTRIDE;
#pragma unroll
            for (int kb = 0; kb < BK; kb += 8) {
                uint32_t af[2][4];
#pragma unroll
                for (int mt = 0; mt < 2; mt++) {
                    const int base = (mt * 16 + g) * TSTRIDE + kb + t;
                    af[mt][0] = __float_as_uint(as[base]);
                    af[mt][1] = __float_as_uint(as[base + 8 * TSTRIDE]);
                    af[mt][2] = __float_as_uint(as[base + 4]);
                    af[mt][3] = __float_as_uint(as[base + 8 * TSTRIDE + 4]);
                }
                uint32_t bf[8][2];
#pragma unroll
                for (int nt = 0; nt < 8; nt++) {
                    const int base = (nt * 8 + g) * TSTRIDE + kb + t;
                    bf[nt][0] = __float_as_uint(bs[base]);
                    bf[nt][1] = __float_as_uint(bs[base + 4]);
                }
#pragma unroll
                for (int mt = 0; mt < 2; mt++)
#pragma unroll
                    for (int nt = 0; nt < 8; nt++)
                        mma_tf32(acc[mt][nt], af[mt], bf[nt]);
            }
        }

        if (s + 1 < NS) {
            const int buf = (s + 1) & 1;
            float* as = sm + buf * TILE_F;
            float* bs = sm + 2 * TILE_F + buf * TILE_F;
#pragma unroll
            for (int i = 0; i < 4; i++) {
                const int o = (i * 32 + r0) * TSTRIDE + c4 * 4;
                as[o+0]=to_tf32(ra[i].x); as[o+1]=to_tf32(ra[i].y); as[o+2]=to_tf32(ra[i].z); as[o+3]=to_tf32(ra[i].w);
                bs[o+0]=to_tf32(rb[i].x); bs[o+1]=to_tf32(rb[i].y); bs[o+2]=to_tf32(rb[i].z); bs[o+3]=to_tf32(rb[i].w);
            }
            __syncthreads();
        }
    }

    // epilogue: bias (+GELU), float2 stores (32B/4-lane segments, sector-aligned)
#pragma unroll
    for (int nt = 0; nt < 8; nt++) {
        const int col = wn * 64 + nt * 8 + 2 * t;
        const float2 bv = *(const float2*)(bias + col);
#pragma unroll
        for (int mt = 0; mt < 2; mt++) {
            const int r = wm * 32 + mt * 16 + g;
            float2 v0, v1;
            v0.x = acc[mt][nt][0] + bv.x; v0.y = acc[mt][nt][1] + bv.y;
            v1.x = acc[mt][nt][2] + bv.x; v1.y = acc[mt][nt][3] + bv.y;
            if (GELU) {
                v0.x = gelu_erf(v0.x); v0.y = gelu_erf(v0.y);
                v1.x = gelu_erf(v1.x); v1.y = gelu_erf(v1.y);
            }
            *(float2*)(out + (size_t)r * ldOut + col) = v0;
            *(float2*)(out + (size_t)(r + 8) * ldOut + col) = v1;
        }
    }
}

// ---------------- kernel 1: h = gelu(X @ fc1_w^T + b) ----------------
__global__ void __launch_bounds__(256, 1) fc1_kernel(
    const float* __restrict__ X,
    const float* __restrict__ W,
    const float* __restrict__ bias)
{
    const int bm = blockIdx.y * BM;
    const int bn = blockIdx.x * BN;
    gemm_tf32<true>(X + (size_t)bm * K1, K1,
                    W + (size_t)bn * K1, K1, K1,
                    g_h + (size_t)bm * H_DIM + bn, H_DIM, bias + bn);
}

// ---------------- kernel 2: fused shared fc2 + expert ----------------
// jobs 0..383:   shared: m=job>>2 (96 tiles), n=job&3 -> cols [n*128,+128)
// jobs 384..639: expert: per batch, 2 overlapping M=128 tiles x 2 N-tiles
__global__ void __launch_bounds__(256, 1) fc2_kernel(
    const float* __restrict__ fc2_w,
    const float* __restrict__ fc2_b,
    const float* __restrict__ ew,
    const float* __restrict__ eb,
    float* __restrict__ out)
{
    const int job = blockIdx.x;
    int bm, outcol;
    const float* Bb;
    const float* bp;
    if (job < 384) {
        const int m = job >> 2, n = job & 3;
        bm = m * 128;
        outcol = n * 128;
        Bb = fc2_w + (size_t)outcol * H_DIM;
        bp = fc2_b + outcol;
    } else {
        const int j = job - 384;
        const int b = j >> 2, mt = (j >> 1) & 1, nt = j & 1;
        bm = b * S_LEN + mt * 64;            // rows 0-127 / 64-191 of batch (overlap writes identical bytes)
        const int nb = nt * 128;
        const int e = g_idx[b];
        Bb = ew + ((size_t)e * N_PART + nb) * H_DIM;
        bp = eb + (size_t)e * N_PART + nb;
        outcol = N_SHARED + nb;
    }
    gemm_tf32<false>(g_h + (size_t)bm * H_DIM, H_DIM,
                     Bb, H_DIM, H_DIM,
                     out + (size_t)bm * D_OUT + outcol, D_OUT, bp);
}

// ---------------- launch ----------------
extern "C" void kernel_launch(void* const* d_in, const int* in_sizes, int n_in,
                              void* d_out, int out_size)
{
    (void)in_sizes; (void)n_in; (void)out_size;
    const float* hs    = (const float*)d_in[0];
    const int*   raw   = (const int*)d_in[1];
    const float* fc1_w = (const float*)d_in[2];
    const float* fc1_b = (const float*)d_in[3];
    const float* fc2_w = (const float*)d_in[4];
    const float* fc2_b = (const float*)d_in[5];
    const float* ew    = (const float*)d_in[6];
    const float* eb    = (const float*)d_in[7];
    float*       out   = (float*)d_out;

    static bool attr_set = false;
    if (!attr_set) {
        cudaFuncSetAttribute(fc1_kernel, cudaFuncAttributeMaxDynamicSharedMemorySize, SMEM_BYTES);
        cudaFuncSetAttribute(fc2_kernel, cudaFuncAttributeMaxDynamicSharedMemorySize, SMEM_BYTES);
        attr_set = true;
    }

    decode_idx_kernel<<<1, B_TOT>>>(raw);

    dim3 g1(H_DIM / BN, M_TOT / BM);     // (24, 96)
    fc1_kernel<<<g1, 256, SMEM_BYTES>>>(hs, fc1_w, fc1_b);

    fc2_kernel<<<640, 256, SMEM_BYTES>>>(fc2_w, fc2_b, ew, eb, out);
}